// round 13
// baseline (speedup 1.0000x reference)
#include <cuda_runtime.h>
#include <math_constants.h>
#include <cstdint>

// ---------------------------------------------------------------------------
// Problem constants
// ---------------------------------------------------------------------------
#define BQ      1024
#define NKEYS   131072
#define DIM     256
#define TOPK    8

#define TILE     128               // keys per MMA tile
#define TOTTILES (NKEYS/TILE)      // 1024
#define KT       18                // key slices (uneven tile ranges)
#define TQ       128               // queries per CTA
#define QT       (BQ/TQ)           // 8 query tiles -> grid 18x8 = 144 CTAs
#define NTHREADS 512               // 16 warps: 8 (m) x 2 (n)
#define KEEP     6                 // per-thread kept candidates per query row
#define SCAND    12                // candidates kept per (query, slice)
#define NCAND    (KT*SCAND)        // 216 candidates per query for rescore

// Score-kernel dynamic smem (bytes). int8 row = 256 B.
// Q tile 128 rows = 32 KB; three K buffers (128 rows) 32 KB each. 128 KB.
#define SM_Q    0
#define SM_K    32768
#define KBUFSZ  32768
#define SM_TOTAL (32768 + 3*KBUFSZ)   // 131072

// ---------------------------------------------------------------------------
// Static device scratch (no allocations allowed)
// ---------------------------------------------------------------------------
__device__ uint32_t g_k8[(size_t)NKEYS * DIM / 4];  // keys * (508/||k||), s8
__device__ uint32_t g_q8[(size_t)BQ * DIM / 4];     // query * 31.75, s8
__device__ float    g_kscale[NKEYS];                // 1/max(||k||,eps), 0 if invalid
__device__ float2   g_part[(size_t)BQ * KT * SCAND];

// ---------------------------------------------------------------------------
// Helpers
// ---------------------------------------------------------------------------
__device__ __forceinline__ uint32_t smem_u32(const void* p) {
    uint32_t a;
    asm("{ .reg .u64 t; cvta.to.shared.u64 t, %1; cvt.u32.u64 %0, t; }" : "=r"(a) : "l"(p));
    return a;
}
#define CP16(dst, src)  asm volatile("cp.async.cg.shared.global [%0], [%1], 16;" :: "r"(dst), "l"(src) : "memory")
#define CP_COMMIT()     asm volatile("cp.async.commit_group;" ::: "memory")
#define CP_WAIT(n)      asm volatile("cp.async.wait_group %0;" :: "n"(n) : "memory")

__device__ __forceinline__ void ldsm_x4(uint32_t& r0, uint32_t& r1,
                                        uint32_t& r2, uint32_t& r3, uint32_t addr) {
    asm volatile("ldmatrix.sync.aligned.m8n8.x4.shared.b16 {%0,%1,%2,%3}, [%4];"
                 : "=r"(r0), "=r"(r1), "=r"(r2), "=r"(r3) : "r"(addr));
}
// s8 x s8 -> s32 accumulate, m16n8k32
__device__ __forceinline__ void mma_s8(int* c,
                                       uint32_t a0, uint32_t a1,
                                       uint32_t a2, uint32_t a3,
                                       uint32_t b0, uint32_t b1) {
    asm volatile("mma.sync.aligned.m16n8k32.row.col.s32.s8.s8.s32 "
                 "{%0,%1,%2,%3}, {%4,%5,%6,%7}, {%8,%9}, {%0,%1,%2,%3};"
                 : "+r"(c[0]), "+r"(c[1]), "+r"(c[2]), "+r"(c[3])
                 : "r"(a0), "r"(a1), "r"(a2), "r"(a3), "r"(b0), "r"(b1));
}
// Swizzled byte offset inside an 8-bit tile with 256 B rows (256 elems).
// c16 = 16-byte chunk 0..15; XOR low 3 chunk bits with row&7.
// (This 8-bit k32 fragment addressing was correctness-validated in R9.)
__device__ __forceinline__ uint32_t tile_off8(int row, int c16) {
    return (uint32_t)(row * 256) + (uint32_t)(((c16 & 7) ^ (row & 7)) << 4)
         + (uint32_t)((c16 >> 3) << 7);
}

__device__ __forceinline__ int q8clamp(float x) {
    int v = __float2int_rn(x);
    return max(-127, min(127, v));
}
__device__ __forceinline__ uint32_t pack_s8x4(float x, float y, float z, float w) {
    return (uint32_t)(q8clamp(x) & 0xff)
         | ((uint32_t)(q8clamp(y) & 0xff) << 8)
         | ((uint32_t)(q8clamp(z) & 0xff) << 16)
         | ((uint32_t)(q8clamp(w) & 0xff) << 24);
}

// ---------------------------------------------------------------------------
// Kernel A1: keys fp32 -> s8 scaled by 508/||k|| (clip +-127); writes g_kscale.
// One warp per key row. `valid` may be int8-bool or int32-bool (detect).
// ---------------------------------------------------------------------------
__global__ void convert_keys_kernel(const float* __restrict__ keys,
                                    const unsigned char* __restrict__ valid)
{
    int w    = (blockIdx.x * blockDim.x + threadIdx.x) >> 5;
    int lane = threadIdx.x & 31;
    if (w >= NKEYS) return;
    const float* kr = keys + (size_t)w * DIM;
    float4 a = *(const float4*)(kr + lane * 8);
    float4 b = *(const float4*)(kr + lane * 8 + 4);
    float ss = a.x*a.x + a.y*a.y + a.z*a.z + a.w*a.w
             + b.x*b.x + b.y*b.y + b.z*b.z + b.w*b.w;
    #pragma unroll
    for (int off = 16; off; off >>= 1) ss += __shfl_xor_sync(0xffffffffu, ss, off);
    bool is32 = ((valid[1] | valid[2] | valid[3]) == 0);
    bool ok   = is32 ? (((const int*)valid)[w] != 0) : (valid[w] != 0);
    float s = ok ? (1.0f / fmaxf(sqrtf(ss), 1e-12f)) : 0.0f;
    if (lane == 0) g_kscale[w] = s;

    float s2 = s * 508.0f;                   // k-hat components ~N(0, 1/16): 4-sigma clip
    uint2 pack;
    pack.x = pack_s8x4(a.x * s2, a.y * s2, a.z * s2, a.w * s2);
    pack.y = pack_s8x4(b.x * s2, b.y * s2, b.z * s2, b.w * s2);
    *(uint2*)(g_k8 + (size_t)w * (DIM/4) + lane * 2) = pack;
}

// Kernel A2: query fp32 -> s8 * 31.75 (per-query positive scale is rank-neutral)
__global__ void convert_q_kernel(const float* __restrict__ query)
{
    int q = blockIdx.x, t = threadIdx.x;     // 64 threads: 4 dims each
    const float* qr = query + (size_t)q * DIM + t * 4;
    g_q8[(size_t)q * (DIM/4) + t] =
        pack_s8x4(qr[0]*31.75f, qr[1]*31.75f, qr[2]*31.75f, qr[3]*31.75f);
}

// ---------------------------------------------------------------------------
// Kernel B: int8 IMMA scoring, Q fragments resident in registers.
// Grid (KT=18, QT=8) = 144 CTAs. CTA: 128 q x ~57 key tiles, 3-stage ring.
// Warp w (of 16): m16 rows at (w&7)*16, n64 cols at (w>>3)*64.
// Per tile per warp: 32 B-ldsm + 64 IMMA (k32); zero A loads.
// ---------------------------------------------------------------------------
__global__ void __launch_bounds__(NTHREADS, 1)
score_mma_kernel()
{
    extern __shared__ char smem[];
    const uint32_t sb = smem_u32(smem);
    const int tid  = threadIdx.x, w = tid >> 5, lane = tid & 31;
    const int mw   = (w & 7) * 16;        // warp m base (query rows)
    const int nw   = (w >> 3) * 64;       // warp n base (key cols)
    const int slice = blockIdx.x;
    const int qb    = blockIdx.y * TQ;
    const int tstart = (slice * TOTTILES) / KT;
    const int tend   = ((slice + 1) * TOTTILES) / KT;
    const int nt     = tend - tstart;     // 56 or 57
    const char* k8 = (const char*)g_k8;
    const char* q8 = (const char*)g_q8;

    // ---- Prologue: Q + K0 (group0), K1 (group1), K2 (group2)
    {
        size_t qsrc = __cvta_generic_to_global(q8 + (size_t)qb * 256);
        #pragma unroll
        for (int m = 0; m < 4; m++) {     // Q: 128 rows x 16 c16 = 2048
            int idx = m * NTHREADS + tid;
            int row = idx >> 4, c16 = idx & 15;
            CP16(sb + SM_Q + tile_off8(row, c16), qsrc + (size_t)row * 256 + c16 * 16);
        }
        #pragma unroll
        for (int s = 0; s < 3; s++) {
            size_t ksrc = __cvta_generic_to_global(
                k8 + (size_t)(tstart + s) * TILE * 256);
            #pragma unroll
            for (int m = 0; m < 4; m++) { // K: 128 rows x 16 c16 = 2048
                int idx = m * NTHREADS + tid;
                int row = idx >> 4, c16 = idx & 15;
                CP16(sb + SM_K + s * KBUFSZ + tile_off8(row, c16),
                     ksrc + (size_t)row * 256 + c16 * 16);
            }
            CP_COMMIT();
        }
    }

    // ldmatrix lane address components (8-bit k32 mapping validated in R9)
    const int a_r  = lane & 15;
    const int a_kc = lane >> 4;
    const int b_r  = (lane & 7) + ((lane >> 4) & 1) * 8;
    const int b_kc = (lane >> 3) & 1;

    // ---- Wait for Q+K0 (<=2 groups pending), preload A frags (32 regs)
    CP_WAIT(2);
    __syncthreads();
    uint32_t aF[8][4];
    #pragma unroll
    for (int ks = 0; ks < 8; ks++)        // 8 k32 steps cover DIM=256
        ldsm_x4(aF[ks][0], aF[ks][1], aF[ks][2], aF[ks][3],
                sb + SM_Q + tile_off8(mw + a_r, ks * 2 + a_kc));

    // Per-thread top-KEEP for 2 query rows (hi = 0/1 -> rows lane>>2, +8)
    int thr[2];
    int ts[2][KEEP]; int ti[2][KEEP];
    #pragma unroll
    for (int i = 0; i < 2; i++) {
        thr[i] = INT_MIN;
        #pragma unroll
        for (int j = 0; j < KEEP; j++) { ts[i][j] = INT_MIN; ti[i][j] = -1; }
    }

    for (int i = 0; i < nt; i++) {
        if (i + 2 < nt)      CP_WAIT(2);
        else if (i + 1 < nt) CP_WAIT(1);
        else                 CP_WAIT(0);
        __syncthreads();
        const uint32_t kbuf = sb + SM_K + (i % 3) * KBUFSZ;

        int acc[8][4];                       // [n8 block][2 rows x 2 cols]
        #pragma unroll
        for (int nb = 0; nb < 8; nb++)
            #pragma unroll
            for (int f = 0; f < 4; f++) acc[nb][f] = 0;

        #pragma unroll
        for (int ks = 0; ks < 8; ks++) {     // 32 dims per step, n64 in 2 halves
            #pragma unroll
            for (int nh = 0; nh < 2; nh++) {
                uint32_t b0, b1, b2, b3, b4, b5, b6, b7;
                int nb0 = nw + nh * 32;
                ldsm_x4(b0, b1, b2, b3, kbuf + tile_off8(nb0 + b_r,      ks * 2 + b_kc));
                ldsm_x4(b4, b5, b6, b7, kbuf + tile_off8(nb0 + 16 + b_r, ks * 2 + b_kc));
                mma_s8(acc[nh*4+0], aF[ks][0], aF[ks][1], aF[ks][2], aF[ks][3], b0, b1);
                mma_s8(acc[nh*4+1], aF[ks][0], aF[ks][1], aF[ks][2], aF[ks][3], b2, b3);
                mma_s8(acc[nh*4+2], aF[ks][0], aF[ks][1], aF[ks][2], aF[ks][3], b4, b5);
                mma_s8(acc[nh*4+3], aF[ks][0], aF[ks][1], aF[ks][2], aF[ks][3], b6, b7);
            }
        }

        __syncthreads();                     // everyone done reading kbuf
        if (i + 3 < nt) {                    // prefetch tile i+3 into freed buffer
            size_t ksrc = __cvta_generic_to_global(
                k8 + (size_t)(tstart + i + 3) * TILE * 256);
            #pragma unroll
            for (int m = 0; m < 4; m++) {
                int idx = m * NTHREADS + tid;
                int row = idx >> 4, c16 = idx & 15;
                CP16(kbuf + tile_off8(row, c16), ksrc + (size_t)row * 256 + c16 * 16);
            }
            CP_COMMIT();
        }

        // Fold: int max screen per row; full fold only if screen passes.
        const int colbase = (tstart + i) * TILE + nw + (lane & 3) * 2;
        #pragma unroll
        for (int hi = 0; hi < 2; hi++) {
            int m0 = max(max(acc[0][hi*2], acc[0][hi*2+1]), max(acc[1][hi*2], acc[1][hi*2+1]));
            int m1 = max(max(acc[2][hi*2], acc[2][hi*2+1]), max(acc[3][hi*2], acc[3][hi*2+1]));
            int m2 = max(max(acc[4][hi*2], acc[4][hi*2+1]), max(acc[5][hi*2], acc[5][hi*2+1]));
            int m3 = max(max(acc[6][hi*2], acc[6][hi*2+1]), max(acc[7][hi*2], acc[7][hi*2+1]));
            if (max(max(m0, m1), max(m2, m3)) > thr[hi]) {   // rare path
                #pragma unroll
                for (int nb = 0; nb < 8; nb++)
                    #pragma unroll
                    for (int e = 0; e < 2; e++) {
                        int sc = acc[nb][hi * 2 + e];
                        if (sc > thr[hi]) {
                            int key = colbase + nb * 8 + e;
                            int ms = 0; int mv = ts[hi][0];
                            #pragma unroll
                            for (int t = 1; t < KEEP; t++)
                                if (ts[hi][t] < mv) { mv = ts[hi][t]; ms = t; }
                            ts[hi][ms] = sc; ti[hi][ms] = key;
                            mv = ts[hi][0];
                            #pragma unroll
                            for (int t = 1; t < KEEP; t++) mv = min(mv, ts[hi][t]);
                            thr[hi] = mv;
                        }
                    }
            }
        }
    }

    // ---- Merge: 8 holders x KEEP per query row -> top-SCAND per (q,slice)
    // int scores < 2^24 are exactly representable as float. 128 rows x 48 f2 = 48 KB.
    __syncthreads();
    float2* Cand = (float2*)smem;
    const int holder = (w >> 3) * 4 + (lane & 3);
    #pragma unroll
    for (int hi = 0; hi < 2; hi++) {
        int row = mw + (lane >> 2) + hi * 8;
        float2* dst = Cand + row * (8 * KEEP) + holder * KEEP;
        #pragma unroll
        for (int j = 0; j < KEEP; j++)
            dst[j] = make_float2(ti[hi][j] < 0 ? -CUDART_INF_F : (float)ts[hi][j],
                                 __int_as_float(ti[hi][j]));
    }
    __syncthreads();

    if (tid < TQ) {
        const float2* c = Cand + tid * (8 * KEEP);
        float bthr = -CUDART_INF_F;
        float bs[SCAND]; int bi[SCAND];
        #pragma unroll
        for (int j = 0; j < SCAND; j++) { bs[j] = -CUDART_INF_F; bi[j] = -1; }
        for (int t = 0; t < 8 * KEEP; t++) {
            float sc = c[t].x;
            if (sc > bthr) {
                int ms = 0; float mv = bs[0];
                #pragma unroll
                for (int u = 1; u < SCAND; u++)
                    if (bs[u] < mv) { mv = bs[u]; ms = u; }
                bs[ms] = sc; bi[ms] = __float_as_int(c[t].y);
                mv = bs[0];
                #pragma unroll
                for (int u = 1; u < SCAND; u++) mv = fminf(mv, bs[u]);
                bthr = mv;
            }
        }
        float2* dst = g_part + ((size_t)(qb + tid) * KT + slice) * SCAND;
        #pragma unroll
        for (int j = 0; j < SCAND; j++)
            dst[j] = make_float2(bs[j], __int_as_float(bi[j]));
    }
}

// ---------------------------------------------------------------------------
// Kernel C: exact fp32 rescore of 216 candidates per query, exact top-8 with
// (score desc, index asc) tie-break, then gather keys+values.
// ---------------------------------------------------------------------------
#define RT 256
__global__ void __launch_bounds__(RT) rescore_kernel(
    const float* __restrict__ query, const float* __restrict__ keys,
    const float* __restrict__ values, float* __restrict__ out)
{
    __shared__ __align__(16) float qs[DIM];
    __shared__ float sc[RT];
    __shared__ int   si[RT];
    __shared__ float rs[RT];
    __shared__ int   ri[RT];
    __shared__ int   rp[RT];
    __shared__ int   topidx[TOPK];

    const int q = blockIdx.x, tid = threadIdx.x, w = tid >> 5, l = tid & 31;

    qs[tid] = query[(size_t)q * DIM + tid];
    sc[tid] = -CUDART_INF_F;
    if (tid < NCAND) {
        float2 c = g_part[(size_t)q * NCAND + tid];
        si[tid] = __float_as_int(c.y);
    } else {
        si[tid] = -1;
    }
    __syncthreads();

    // Warp-per-candidate exact scoring: 8 warps x 27 candidates
    for (int cc = w * 27; cc < w * 27 + 27; cc++) {
        int idx = si[cc];
        float s = -CUDART_INF_F;
        if (idx >= 0) {
            float ksc = g_kscale[idx];
            const float* kr = keys + (size_t)idx * DIM;
            float4 ka = *(const float4*)(kr + l * 8);
            float4 kb = *(const float4*)(kr + l * 8 + 4);
            float4 qa = ((const float4*)qs)[l * 2];
            float4 qb = ((const float4*)qs)[l * 2 + 1];
            float p = ka.x*qa.x + ka.y*qa.y + ka.z*qa.z + ka.w*qa.w
                    + kb.x*qb.x + kb.y*qb.y + kb.z*qb.z + kb.w*qb.w;
            #pragma unroll
            for (int off = 16; off; off >>= 1) p += __shfl_xor_sync(0xffffffffu, p, off);
            s = (ksc == 0.0f) ? -CUDART_INF_F : p * ksc;
        }
        if (l == 0) sc[cc] = s;
    }
    __syncthreads();

    // 8 rounds of exact argmax with index tie-break
    for (int r = 0; r < TOPK; r++) {
        float s = sc[tid];
        rs[tid] = s;
        ri[tid] = (s == -CUDART_INF_F) ? 0x7fffffff : si[tid];
        rp[tid] = tid;
        __syncthreads();
        for (int off = RT / 2; off > 0; off >>= 1) {
            if (tid < off) {
                float s2 = rs[tid + off]; int ix2 = ri[tid + off];
                if (s2 > rs[tid] || (s2 == rs[tid] && ix2 < ri[tid])) {
                    rs[tid] = s2; ri[tid] = ix2; rp[tid] = rp[tid + off];
                }
            }
            __syncthreads();
        }
        if (tid == 0) {
            topidx[r] = ri[0];
            sc[rp[0]] = -CUDART_INF_F;           // consume winner
        }
        __syncthreads();
    }

    // Gather: out = [gathered_keys (B,K,D) | gathered_vals (B,K,D)]
    const size_t GK = (size_t)BQ * TOPK * DIM;
    for (int i = tid; i < TOPK * DIM / 4; i += RT) {
        int j  = i >> 6;
        int c4 = i & 63;
        int ix = topidx[j];
        if (ix < 0 || ix == 0x7fffffff) ix = 0;  // defensive
        float4 kv = *(const float4*)(keys   + (size_t)ix * DIM + c4 * 4);
        float4 vv = *(const float4*)(values + (size_t)ix * DIM + c4 * 4);
        *(float4*)(out +      ((size_t)q * TOPK + j) * DIM + c4 * 4) = kv;
        *(float4*)(out + GK + ((size_t)q * TOPK + j) * DIM + c4 * 4) = vv;
    }
}

// ---------------------------------------------------------------------------
extern "C" void kernel_launch(void* const* d_in, const int* in_sizes, int n_in,
                              void* d_out, int out_size)
{
    const float*         query  = (const float*)d_in[0];
    const float*         keys   = (const float*)d_in[1];
    const float*         values = (const float*)d_in[2];
    const unsigned char* valid  = (const unsigned char*)d_in[3];
    // d_in[4] (top_k) fixed at 8.

    cudaFuncSetAttribute(score_mma_kernel,
                         cudaFuncAttributeMaxDynamicSharedMemorySize, SM_TOTAL);

    convert_keys_kernel<<<NKEYS / 8, 256>>>(keys, valid);
    convert_q_kernel<<<BQ, 64>>>(query);
    dim3 grid(KT, QT);
    score_mma_kernel<<<grid, NTHREADS, SM_TOTAL>>>();
    rescore_kernel<<<BQ, RT>>>(query, keys, values, (float*)d_out);
}

// round 16
// speedup vs baseline: 1.9578x; 1.9578x over previous
#include <cuda_runtime.h>
#include <cuda_fp16.h>
#include <math_constants.h>
#include <cstdint>

// ---------------------------------------------------------------------------
// Problem constants
// ---------------------------------------------------------------------------
#define BQ      1024
#define NKEYS   131072
#define DIM     256
#define TOPK    8

#define TILE     128               // keys per MMA tile
#define TOTTILES (NKEYS/TILE)      // 1024
#define KT       18                // key slices (uneven tile ranges)
#define TQ       128               // queries per CTA
#define QT       (BQ/TQ)           // 8 query tiles -> grid 18x8 = 144 CTAs
#define NTHREADS 512               // 16 warps: 8 (m) x 2 (n)
#define KEEP     4                 // per-thread kept candidates per query row
#define NCAND    (KT*TOPK)         // 144 candidates per query
#define PRUNE    24                // exact-rescored candidates per query

// Score-kernel dynamic smem (bytes). Row = 256 f16 = 512 B.
// Q tile 128 rows = 64 KB (recycled as 3rd K ring buffer after A preload);
// two dedicated K buffers 64 KB each. 192 KB.
#define SM_Q    0
#define SM_K0   65536
#define SM_K1   131072
#define SM_TOTAL 196608

// ---------------------------------------------------------------------------
// Static device scratch (no allocations allowed)
// ---------------------------------------------------------------------------
__device__ __half g_kbf[(size_t)NKEYS * DIM];   // keys * (1/||k||), f16
__device__ __half g_qbf[(size_t)BQ * DIM];      // query, f16
__device__ float  g_kscale[NKEYS];              // 1/max(||k||,eps), 0 if invalid
__device__ float2 g_part[(size_t)BQ * KT * TOPK];

// ---------------------------------------------------------------------------
// Helpers
// ---------------------------------------------------------------------------
__device__ __forceinline__ uint32_t smem_u32(const void* p) {
    uint32_t a;
    asm("{ .reg .u64 t; cvta.to.shared.u64 t, %1; cvt.u32.u64 %0, t; }" : "=r"(a) : "l"(p));
    return a;
}
#define CP16(dst, src)  asm volatile("cp.async.cg.shared.global [%0], [%1], 16;" :: "r"(dst), "l"(src) : "memory")
#define CP_COMMIT()     asm volatile("cp.async.commit_group;" ::: "memory")
#define CP_WAIT(n)      asm volatile("cp.async.wait_group %0;" :: "n"(n) : "memory")

__device__ __forceinline__ void ldsm_x4(uint32_t& r0, uint32_t& r1,
                                        uint32_t& r2, uint32_t& r3, uint32_t addr) {
    asm volatile("ldmatrix.sync.aligned.m8n8.x4.shared.b16 {%0,%1,%2,%3}, [%4];"
                 : "=r"(r0), "=r"(r1), "=r"(r2), "=r"(r3) : "r"(addr));
}
// f16 x f16 -> f16 accumulate (D,C packed f16x2 pairs)
__device__ __forceinline__ void mma16816_f16(uint32_t& c0, uint32_t& c1,
                                             uint32_t a0, uint32_t a1,
                                             uint32_t a2, uint32_t a3,
                                             uint32_t b0, uint32_t b1) {
    asm volatile("mma.sync.aligned.m16n8k16.row.col.f16.f16.f16.f16 "
                 "{%0,%1}, {%2,%3,%4,%5}, {%6,%7}, {%0,%1};"
                 : "+r"(c0), "+r"(c1)
                 : "r"(a0), "r"(a1), "r"(a2), "r"(a3), "r"(b0), "r"(b1));
}
// Swizzled byte offset inside a tile with 512 B rows (256 f16).
// c16 = 16-byte chunk 0..31; XOR low 3 chunk bits with row&7 (validated R6-R11).
__device__ __forceinline__ uint32_t tile_off(int row, int c16) {
    return (uint32_t)(row * 512) + (uint32_t)(((c16 & 7) ^ (row & 7)) << 4)
         + (uint32_t)((c16 >> 3) << 7);
}

// ---------------------------------------------------------------------------
// Kernel A1: keys fp32 -> f16 pre-scaled by 1/||k||; writes g_kscale.
// One warp per key row. `valid` may be int8-bool or int32-bool (detect).
// ---------------------------------------------------------------------------
__global__ void convert_keys_kernel(const float* __restrict__ keys,
                                    const unsigned char* __restrict__ valid)
{
    int w    = (blockIdx.x * blockDim.x + threadIdx.x) >> 5;
    int lane = threadIdx.x & 31;
    if (w >= NKEYS) return;
    const float* kr = keys + (size_t)w * DIM;
    float4 a = *(const float4*)(kr + lane * 8);
    float4 b = *(const float4*)(kr + lane * 8 + 4);
    float ss = a.x*a.x + a.y*a.y + a.z*a.z + a.w*a.w
             + b.x*b.x + b.y*b.y + b.z*b.z + b.w*b.w;
    #pragma unroll
    for (int off = 16; off; off >>= 1) ss += __shfl_xor_sync(0xffffffffu, ss, off);
    bool is32 = ((valid[1] | valid[2] | valid[3]) == 0);
    bool ok   = is32 ? (((const int*)valid)[w] != 0) : (valid[w] != 0);
    float s = ok ? (1.0f / fmaxf(sqrtf(ss), 1e-12f)) : 0.0f;
    if (lane == 0) g_kscale[w] = s;

    __half2 p0 = __floats2half2_rn(a.x * s, a.y * s);
    __half2 p1 = __floats2half2_rn(a.z * s, a.w * s);
    __half2 p2 = __floats2half2_rn(b.x * s, b.y * s);
    __half2 p3 = __floats2half2_rn(b.z * s, b.w * s);
    uint4 pack;
    pack.x = *(uint32_t*)&p0; pack.y = *(uint32_t*)&p1;
    pack.z = *(uint32_t*)&p2; pack.w = *(uint32_t*)&p3;
    *(uint4*)(g_kbf + (size_t)w * DIM + lane * 8) = pack;
}

// Kernel A2: query fp32 -> f16 (per-query positive scale is rank-neutral)
__global__ void convert_q_kernel(const float* __restrict__ query)
{
    int q = blockIdx.x, t = threadIdx.x;
    g_qbf[(size_t)q * DIM + t] = __float2half_rn(query[(size_t)q * DIM + t]);
}

// ---------------------------------------------------------------------------
// Kernel B: f16 mma.sync scoring, Q fragments resident in registers.
// Grid (KT=18, QT=8) = 144 CTAs. CTA: 128 q x ~57 key tiles.
// Warp w (of 16): m16 rows at (w&7)*16, n64 cols at (w>>3)*64.
// 3-stage K ring: after A-fragment preload, the Q smem becomes buffer 2.
// ---------------------------------------------------------------------------
__global__ void __launch_bounds__(NTHREADS, 1)
score_mma_kernel()
{
    extern __shared__ char smem[];
    const uint32_t sb = smem_u32(smem);
    const int tid  = threadIdx.x, w = tid >> 5, lane = tid & 31;
    const int mw   = (w & 7) * 16;        // warp m base (query rows)
    const int nw   = (w >> 3) * 64;       // warp n base (key cols)
    const int slice = blockIdx.x;
    const int qb    = blockIdx.y * TQ;
    const int tstart = (slice * TOTTILES) / KT;
    const int tend   = ((slice + 1) * TOTTILES) / KT;
    const int nt     = tend - tstart;     // 56 or 57

    const uint32_t kb3[3] = { sb + SM_K0, sb + SM_K1, sb + SM_Q };

    // ---- Prologue: G0 = Q + K tile0; G1 = K tile1
    {
        size_t qsrc = __cvta_generic_to_global(g_qbf + (size_t)qb * DIM);
        size_t ksrc = __cvta_generic_to_global(g_kbf + (size_t)tstart * TILE * DIM);
        #pragma unroll
        for (int m = 0; m < 8; m++) {     // Q: 128 rows x 32 c16 = 4096
            int idx = m * NTHREADS + tid;
            int row = idx >> 5, c16 = idx & 31;
            CP16(sb + SM_Q + tile_off(row, c16), qsrc + (size_t)row * (DIM*2) + c16 * 16);
        }
        #pragma unroll
        for (int m = 0; m < 8; m++) {     // K0
            int idx = m * NTHREADS + tid;
            int row = idx >> 5, c16 = idx & 31;
            CP16(kb3[0] + tile_off(row, c16), ksrc + (size_t)row * (DIM*2) + c16 * 16);
        }
        CP_COMMIT();
        ksrc = __cvta_generic_to_global(g_kbf + (size_t)(tstart + 1) * TILE * DIM);
        #pragma unroll
        for (int m = 0; m < 8; m++) {     // K1
            int idx = m * NTHREADS + tid;
            int row = idx >> 5, c16 = idx & 31;
            CP16(kb3[1] + tile_off(row, c16), ksrc + (size_t)row * (DIM*2) + c16 * 16);
        }
        CP_COMMIT();
    }

    // ldmatrix lane address components (validated R6-R11)
    const int a_r  = lane & 15;
    const int a_kc = lane >> 4;
    const int b_r  = (lane & 7) + ((lane >> 4) & 1) * 8;
    const int b_kc = (lane >> 3) & 1;

    // ---- Wait for Q+K0 (G1 may stay pending), preload all A fragments
    CP_WAIT(1);
    __syncthreads();
    uint32_t aF[16][4];
    #pragma unroll
    for (int ks = 0; ks < 16; ks++)
        ldsm_x4(aF[ks][0], aF[ks][1], aF[ks][2], aF[ks][3],
                sb + SM_Q + tile_off(mw + a_r, ks * 2 + a_kc));
    __syncthreads();                      // Q smem now dead -> ring buffer 2

    // G2 = K tile2 into recycled Q smem
    {
        size_t ksrc = __cvta_generic_to_global(
            g_kbf + (size_t)(tstart + 2) * TILE * DIM);
        #pragma unroll
        for (int m = 0; m < 8; m++) {
            int idx = m * NTHREADS + tid;
            int row = idx >> 5, c16 = idx & 31;
            CP16(kb3[2] + tile_off(row, c16), ksrc + (size_t)row * (DIM*2) + c16 * 16);
        }
        CP_COMMIT();
    }

    // Per-thread top-KEEP for 2 query rows (hi = 0/1 -> rows lane>>2, +8)
    float thr[2];
    float ts[2][KEEP]; int ti[2][KEEP];
    #pragma unroll
    for (int i = 0; i < 2; i++) {
        thr[i] = -CUDART_INF_F;
        #pragma unroll
        for (int j = 0; j < KEEP; j++) { ts[i][j] = -CUDART_INF_F; ti[i][j] = -1; }
    }

    for (int i = 0; i < nt; i++) {
        if (i + 2 < nt)      CP_WAIT(2);
        else if (i + 1 < nt) CP_WAIT(1);
        else                 CP_WAIT(0);
        __syncthreads();
        const uint32_t kbuf = kb3[i % 3];

        uint32_t acc[8][2];                  // [n8 block][creg], f16x2 packed
        #pragma unroll
        for (int nb = 0; nb < 8; nb++) acc[nb][0] = acc[nb][1] = 0u;

        #pragma unroll
        for (int ks = 0; ks < 16; ks++) {    // 16 dims per step, n64 in 2 halves
            #pragma unroll
            for (int nh = 0; nh < 2; nh++) { // keep only 8 B regs live
                uint32_t b0, b1, b2, b3, b4, b5, b6, b7;
                int nb0 = nw + nh * 32;
                ldsm_x4(b0, b1, b2, b3, kbuf + tile_off(nb0 + b_r,      ks * 2 + b_kc));
                ldsm_x4(b4, b5, b6, b7, kbuf + tile_off(nb0 + 16 + b_r, ks * 2 + b_kc));
                mma16816_f16(acc[nh*4+0][0], acc[nh*4+0][1], aF[ks][0], aF[ks][1], aF[ks][2], aF[ks][3], b0, b1);
                mma16816_f16(acc[nh*4+1][0], acc[nh*4+1][1], aF[ks][0], aF[ks][1], aF[ks][2], aF[ks][3], b2, b3);
                mma16816_f16(acc[nh*4+2][0], acc[nh*4+2][1], aF[ks][0], aF[ks][1], aF[ks][2], aF[ks][3], b4, b5);
                mma16816_f16(acc[nh*4+3][0], acc[nh*4+3][1], aF[ks][0], aF[ks][1], aF[ks][2], aF[ks][3], b6, b7);
            }
        }

        __syncthreads();                     // everyone done reading kbuf
        if (i + 3 < nt) {                    // prefetch tile i+3 into freed buffer
            size_t ksrc = __cvta_generic_to_global(
                g_kbf + (size_t)(tstart + i + 3) * TILE * DIM);
            #pragma unroll
            for (int m = 0; m < 8; m++) {
                int idx = m * NTHREADS + tid;
                int row = idx >> 5, c16 = idx & 31;
                CP16(kbuf + tile_off(row, c16), ksrc + (size_t)row * (DIM*2) + c16 * 16);
            }
            CP_COMMIT();
        }

        // Fold: packed hmax2 screen per row; full fold only if screen passes.
        const int colbase = (tstart + i) * TILE + nw + (lane & 3) * 2;
        #pragma unroll
        for (int hi = 0; hi < 2; hi++) {
            __half2 m01 = __hmax2(*(__half2*)&acc[0][hi], *(__half2*)&acc[1][hi]);
            __half2 m23 = __hmax2(*(__half2*)&acc[2][hi], *(__half2*)&acc[3][hi]);
            __half2 m45 = __hmax2(*(__half2*)&acc[4][hi], *(__half2*)&acc[5][hi]);
            __half2 m67 = __hmax2(*(__half2*)&acc[6][hi], *(__half2*)&acc[7][hi]);
            __half2 m   = __hmax2(__hmax2(m01, m23), __hmax2(m45, m67));
            float2 mf = __half22float2(m);
            if (fmaxf(mf.x, mf.y) > thr[hi]) {       // rare path
                #pragma unroll
                for (int nb = 0; nb < 8; nb++) {
                    float2 v = __half22float2(*(__half2*)&acc[nb][hi]);
                    #pragma unroll
                    for (int e = 0; e < 2; e++) {
                        float sc = e ? v.y : v.x;
                        if (sc > thr[hi]) {
                            int key = colbase + nb * 8 + e;
                            int ms = 0; float mv = ts[hi][0];
                            #pragma unroll
                            for (int t = 1; t < KEEP; t++)
                                if (ts[hi][t] < mv) { mv = ts[hi][t]; ms = t; }
                            ts[hi][ms] = sc; ti[hi][ms] = key;
                            mv = ts[hi][0];
                            #pragma unroll
                            for (int t = 1; t < KEEP; t++) mv = fminf(mv, ts[hi][t]);
                            thr[hi] = mv;
                        }
                    }
                }
            }
        }
    }

    // ---- Merge: 8 holders x KEEP entries per query row -> top-8 per (q,slice)
    __syncthreads();
    float2* Cand = (float2*)smem;            // 128 rows x 32 float2 = 32 KB
    const int holder = (w >> 3) * 4 + (lane & 3);
    #pragma unroll
    for (int hi = 0; hi < 2; hi++) {
        int row = mw + (lane >> 2) + hi * 8;
        float2* dst = Cand + row * (8 * KEEP) + holder * KEEP;
        #pragma unroll
        for (int j = 0; j < KEEP; j++)
            dst[j] = make_float2(ts[hi][j], __int_as_float(ti[hi][j]));
    }
    __syncthreads();

    if (tid < TQ) {
        const float2* c = Cand + tid * (8 * KEEP);
        float bthr = -CUDART_INF_F;
        float bs[8]; int bi[8];
        #pragma unroll
        for (int j = 0; j < 8; j++) { bs[j] = -CUDART_INF_F; bi[j] = -1; }
        for (int t = 0; t < 8 * KEEP; t++) {
            float sc = c[t].x;
            if (sc > bthr) {
                int ms = 0; float mv = bs[0];
                #pragma unroll
                for (int u = 1; u < 8; u++)
                    if (bs[u] < mv) { mv = bs[u]; ms = u; }
                bs[ms] = sc; bi[ms] = __float_as_int(c[t].y);
                mv = bs[0];
                #pragma unroll
                for (int u = 1; u < 8; u++) mv = fminf(mv, bs[u]);
                bthr = mv;
            }
        }
        float2* dst = g_part + ((size_t)(qb + tid) * KT + slice) * TOPK;
        #pragma unroll
        for (int j = 0; j < 8; j++)
            dst[j] = make_float2(bs[j], __int_as_float(bi[j]));
    }
}

// ---------------------------------------------------------------------------
// Kernel C: prune 144 candidates to top-PRUNE by approx score (pairwise rank),
// exact fp32 rescore of those, exact top-8 with (score desc, index asc)
// tie-break, then gather keys+values.
// ---------------------------------------------------------------------------
#define RT 256
__global__ void __launch_bounds__(RT) rescore_kernel(
    const float* __restrict__ query, const float* __restrict__ keys,
    const float* __restrict__ values, float* __restrict__ out)
{
    __shared__ __align__(16) float qs[DIM];
    __shared__ float csc[NCAND];
    __shared__ int   cidx[NCAND];
    __shared__ int   sel[PRUNE];
    __shared__ int   nsel;
    __shared__ float ssc[PRUNE];
    __shared__ float rs[RT];
    __shared__ int   ri[RT];
    __shared__ int   rp[RT];
    __shared__ int   topidx[TOPK];

    const int q = blockIdx.x, tid = threadIdx.x, w = tid >> 5, l = tid & 31;

    qs[tid] = query[(size_t)q * DIM + tid];
    if (tid == 0) nsel = 0;
    if (tid < NCAND) {
        float2 c = g_part[(size_t)q * NCAND + tid];
        csc[tid] = c.x;
        cidx[tid] = __float_as_int(c.y);
    }
    __syncthreads();

    // Pairwise rank by approx score (desc, idx asc); keep rank < PRUNE.
    // All (score, idx) pairs are distinct -> exactly PRUNE selected.
    if (tid < NCAND) {
        float s = csc[tid]; int ix = cidx[tid];
        int rank = 0;
        for (int j = 0; j < NCAND; j++) {
            float sj = csc[j]; int xj = cidx[j];
            rank += (sj > s) || (sj == s && xj < ix);
        }
        if (rank < PRUNE) {
            int p = atomicAdd(&nsel, 1);
            sel[p] = ix;
        }
    }
    __syncthreads();

    // Warp-per-candidate exact scoring: 8 warps x 3 candidates
    for (int cc = w * (PRUNE / 8); cc < (w + 1) * (PRUNE / 8); cc++) {
        int idx = sel[cc];
        float s = -CUDART_INF_F;
        if (idx >= 0) {
            float ksc = g_kscale[idx];
            const float* kr = keys + (size_t)idx * DIM;
            float4 ka = *(const float4*)(kr + l * 8);
            float4 kb = *(const float4*)(kr + l * 8 + 4);
            float4 qa = ((const float4*)qs)[l * 2];
            float4 qb = ((const float4*)qs)[l * 2 + 1];
            float p = ka.x*qa.x + ka.y*qa.y + ka.z*qa.z + ka.w*qa.w
                    + kb.x*qb.x + kb.y*qb.y + kb.z*qb.z + kb.w*qb.w;
            #pragma unroll
            for (int off = 16; off; off >>= 1) p += __shfl_xor_sync(0xffffffffu, p, off);
            s = (ksc == 0.0f) ? -CUDART_INF_F : p * ksc;
        }
        if (l == 0) ssc[cc] = s;
    }
    __syncthreads();

    // 8 rounds of exact argmax over PRUNE entries with index tie-break
    for (int r = 0; r < TOPK; r++) {
        float s = (tid < PRUNE) ? ssc[tid] : -CUDART_INF_F;
        rs[tid] = s;
        ri[tid] = (tid < PRUNE && s != -CUDART_INF_F) ? sel[tid] : 0x7fffffff;
        rp[tid] = tid;
        __syncthreads();
        for (int off = RT / 2; off > 0; off >>= 1) {
            if (tid < off) {
                float s2 = rs[tid + off]; int ix2 = ri[tid + off];
                if (s2 > rs[tid] || (s2 == rs[tid] && ix2 < ri[tid])) {
                    rs[tid] = s2; ri[tid] = ix2; rp[tid] = rp[tid + off];
                }
            }
            __syncthreads();
        }
        if (tid == 0) {
            topidx[r] = ri[0];
            if (rp[0] < PRUNE) ssc[rp[0]] = -CUDART_INF_F;   // consume winner
        }
        __syncthreads();
    }

    // Gather: out = [gathered_keys (B,K,D) | gathered_vals (B,K,D)]
    const size_t GK = (size_t)BQ * TOPK * DIM;
    for (int i = tid; i < TOPK * DIM / 4; i += RT) {
        int j  = i >> 6;
        int c4 = i & 63;
        int ix = topidx[j];
        if (ix < 0 || ix == 0x7fffffff) ix = 0;  // defensive
        float4 kv = *(const float4*)(keys   + (size_t)ix * DIM + c4 * 4);
        float4 vv = *(const float4*)(values + (size_t)ix * DIM + c4 * 4);
        *(float4*)(out +      ((size_t)q * TOPK + j) * DIM + c4 * 4) = kv;
        *(float4*)(out + GK + ((size_t)q * TOPK + j) * DIM + c4 * 4) = vv;
    }
}

// ---------------------------------------------------------------------------
extern "C" void kernel_launch(void* const* d_in, const int* in_sizes, int n_in,
                              void* d_out, int out_size)
{
    const float*         query  = (const float*)d_in[0];
    const float*         keys   = (const float*)d_in[1];
    const float*         values = (const float*)d_in[2];
    const unsigned char* valid  = (const unsigned char*)d_in[3];
    // d_in[4] (top_k) fixed at 8.

    cudaFuncSetAttribute(score_mma_kernel,
                         cudaFuncAttributeMaxDynamicSharedMemorySize, SM_TOTAL);

    convert_keys_kernel<<<NKEYS / 8, 256>>>(keys, valid);
    convert_q_kernel<<<BQ, DIM>>>(query);
    dim3 grid(KT, QT);
    score_mma_kernel<<<grid, NTHREADS, SM_TOTAL>>>();
    rescore_kernel<<<BQ, RT>>>(query, keys, values, (float*)d_out);
}

// round 17
// speedup vs baseline: 1.9946x; 1.0188x over previous
#include <cuda_runtime.h>
#include <cuda_fp16.h>
#include <math_constants.h>
#include <cstdint>

// ---------------------------------------------------------------------------
// Problem constants
// ---------------------------------------------------------------------------
#define BQ      1024
#define NKEYS   131072
#define DIM     256
#define TOPK    8

#define TILE     128               // keys per MMA tile
#define TOTTILES (NKEYS/TILE)      // 1024
#define KT       18                // key slices (uneven tile ranges)
#define TQ       128               // queries per CTA
#define QT       (BQ/TQ)           // 8 query tiles -> grid 18x8 = 144 CTAs
#define NTHREADS 512               // 16 warps: 8 (m) x 2 (n)
#define KEEP     4                 // per-thread kept candidates per query row
#define NCAND    (KT*TOPK)         // 144 candidates per query
#define PRUNE    24                // exact-rescored candidates per query

// Score-kernel dynamic smem (bytes). Row = 256 f16 = 512 B.
// Q tile 128 rows = 64 KB (recycled as 3rd K ring buffer after A preload);
// two dedicated K buffers 64 KB each. 192 KB.
#define SM_Q    0
#define SM_K0   65536
#define SM_K1   131072
#define SM_TOTAL 196608

// ---------------------------------------------------------------------------
// Static device scratch (no allocations allowed)
// ---------------------------------------------------------------------------
__device__ __half g_kbf[(size_t)NKEYS * DIM];   // keys * (1/||k||), f16
__device__ __half g_qbf[(size_t)BQ * DIM];      // query, f16
__device__ float  g_kscale[NKEYS];              // 1/max(||k||,eps), 0 if invalid
__device__ float2 g_part[(size_t)BQ * KT * TOPK];

// ---------------------------------------------------------------------------
// Helpers
// ---------------------------------------------------------------------------
__device__ __forceinline__ uint32_t smem_u32(const void* p) {
    uint32_t a;
    asm("{ .reg .u64 t; cvta.to.shared.u64 t, %1; cvt.u32.u64 %0, t; }" : "=r"(a) : "l"(p));
    return a;
}
#define CP16(dst, src)  asm volatile("cp.async.cg.shared.global [%0], [%1], 16;" :: "r"(dst), "l"(src) : "memory")
#define CP_COMMIT()     asm volatile("cp.async.commit_group;" ::: "memory")
#define CP_WAIT(n)      asm volatile("cp.async.wait_group %0;" :: "n"(n) : "memory")

__device__ __forceinline__ void ldsm_x4(uint32_t& r0, uint32_t& r1,
                                        uint32_t& r2, uint32_t& r3, uint32_t addr) {
    asm volatile("ldmatrix.sync.aligned.m8n8.x4.shared.b16 {%0,%1,%2,%3}, [%4];"
                 : "=r"(r0), "=r"(r1), "=r"(r2), "=r"(r3) : "r"(addr));
}
// f16 x f16 -> f16 accumulate (D,C packed f16x2 pairs)
__device__ __forceinline__ void mma16816_f16(uint32_t& c0, uint32_t& c1,
                                             uint32_t a0, uint32_t a1,
                                             uint32_t a2, uint32_t a3,
                                             uint32_t b0, uint32_t b1) {
    asm volatile("mma.sync.aligned.m16n8k16.row.col.f16.f16.f16.f16 "
                 "{%0,%1}, {%2,%3,%4,%5}, {%6,%7}, {%0,%1};"
                 : "+r"(c0), "+r"(c1)
                 : "r"(a0), "r"(a1), "r"(a2), "r"(a3), "r"(b0), "r"(b1));
}
// Swizzled byte offset inside a tile with 512 B rows (256 f16).
// c16 = 16-byte chunk 0..31; XOR low 3 chunk bits with row&7 (validated R6-R15).
__device__ __forceinline__ uint32_t tile_off(int row, int c16) {
    return (uint32_t)(row * 512) + (uint32_t)(((c16 & 7) ^ (row & 7)) << 4)
         + (uint32_t)((c16 >> 3) << 7);
}

// ---------------------------------------------------------------------------
// Kernel A (fused): blocks [0, NKEYS/8): keys fp32 -> f16 * (1/||k||) +
// g_kscale (one warp per key row). Blocks >= NKEYS/8: query fp32 -> f16.
// `valid` may be int8-bool or int32-bool (detect).
// ---------------------------------------------------------------------------
__global__ void convert_kernel(const float* __restrict__ keys,
                               const float* __restrict__ query,
                               const unsigned char* __restrict__ valid)
{
    if (blockIdx.x >= NKEYS / 8) {           // query conversion blocks
        int i = (blockIdx.x - NKEYS / 8) * 256 + threadIdx.x;
        g_qbf[i] = __float2half_rn(query[i]);
        return;
    }
    int w    = (blockIdx.x * blockDim.x + threadIdx.x) >> 5;
    int lane = threadIdx.x & 31;
    const float* kr = keys + (size_t)w * DIM;
    float4 a = *(const float4*)(kr + lane * 8);
    float4 b = *(const float4*)(kr + lane * 8 + 4);
    float ss = a.x*a.x + a.y*a.y + a.z*a.z + a.w*a.w
             + b.x*b.x + b.y*b.y + b.z*b.z + b.w*b.w;
    #pragma unroll
    for (int off = 16; off; off >>= 1) ss += __shfl_xor_sync(0xffffffffu, ss, off);
    bool is32 = ((valid[1] | valid[2] | valid[3]) == 0);
    bool ok   = is32 ? (((const int*)valid)[w] != 0) : (valid[w] != 0);
    float s = ok ? (1.0f / fmaxf(sqrtf(ss), 1e-12f)) : 0.0f;
    if (lane == 0) g_kscale[w] = s;

    __half2 p0 = __floats2half2_rn(a.x * s, a.y * s);
    __half2 p1 = __floats2half2_rn(a.z * s, a.w * s);
    __half2 p2 = __floats2half2_rn(b.x * s, b.y * s);
    __half2 p3 = __floats2half2_rn(b.z * s, b.w * s);
    uint4 pack;
    pack.x = *(uint32_t*)&p0; pack.y = *(uint32_t*)&p1;
    pack.z = *(uint32_t*)&p2; pack.w = *(uint32_t*)&p3;
    *(uint4*)(g_kbf + (size_t)w * DIM + lane * 8) = pack;
}

// ---------------------------------------------------------------------------
// Kernel B: f16 mma.sync scoring, Q fragments resident in registers.
// Grid (KT=18, QT=8) = 144 CTAs. CTA: 128 q x ~57 key tiles.
// Warp w (of 16): m16 rows at (w&7)*16, n64 cols at (w>>3)*64.
// 3-buffer K ring, prefetch distance 2: the prefetch target buf[(i+2)%3]
// holds tile i-1, whose reads completed before this iteration's (single)
// barrier -> ONE __syncthreads per tile instead of two.
// ---------------------------------------------------------------------------
__global__ void __launch_bounds__(NTHREADS, 1)
score_mma_kernel()
{
    extern __shared__ char smem[];
    const uint32_t sb = smem_u32(smem);
    const int tid  = threadIdx.x, w = tid >> 5, lane = tid & 31;
    const int mw   = (w & 7) * 16;        // warp m base (query rows)
    const int nw   = (w >> 3) * 64;       // warp n base (key cols)
    const int slice = blockIdx.x;
    const int qb    = blockIdx.y * TQ;
    const int tstart = (slice * TOTTILES) / KT;
    const int tend   = ((slice + 1) * TOTTILES) / KT;
    const int nt     = tend - tstart;     // 56 or 57

    const uint32_t kb3[3] = { sb + SM_K0, sb + SM_K1, sb + SM_Q };

    // ---- Prologue: G0 = Q + K tile0; G1 = K tile1
    {
        size_t qsrc = __cvta_generic_to_global(g_qbf + (size_t)qb * DIM);
        size_t ksrc = __cvta_generic_to_global(g_kbf + (size_t)tstart * TILE * DIM);
        #pragma unroll
        for (int m = 0; m < 8; m++) {     // Q: 128 rows x 32 c16 = 4096
            int idx = m * NTHREADS + tid;
            int row = idx >> 5, c16 = idx & 31;
            CP16(sb + SM_Q + tile_off(row, c16), qsrc + (size_t)row * (DIM*2) + c16 * 16);
        }
        #pragma unroll
        for (int m = 0; m < 8; m++) {     // K0
            int idx = m * NTHREADS + tid;
            int row = idx >> 5, c16 = idx & 31;
            CP16(kb3[0] + tile_off(row, c16), ksrc + (size_t)row * (DIM*2) + c16 * 16);
        }
        CP_COMMIT();
        ksrc = __cvta_generic_to_global(g_kbf + (size_t)(tstart + 1) * TILE * DIM);
        #pragma unroll
        for (int m = 0; m < 8; m++) {     // K1
            int idx = m * NTHREADS + tid;
            int row = idx >> 5, c16 = idx & 31;
            CP16(kb3[1] + tile_off(row, c16), ksrc + (size_t)row * (DIM*2) + c16 * 16);
        }
        CP_COMMIT();
    }

    // ldmatrix lane address components (validated R6-R15)
    const int a_r  = lane & 15;
    const int a_kc = lane >> 4;
    const int b_r  = (lane & 7) + ((lane >> 4) & 1) * 8;
    const int b_kc = (lane >> 3) & 1;

    // ---- Wait for Q+K0 (G1 may stay pending), preload all A fragments.
    CP_WAIT(1);
    __syncthreads();
    uint32_t aF[16][4];
    #pragma unroll
    for (int ks = 0; ks < 16; ks++)
        ldsm_x4(aF[ks][0], aF[ks][1], aF[ks][2], aF[ks][3],
                sb + SM_Q + tile_off(mw + a_r, ks * 2 + a_kc));
    // Q smem becomes ring buffer 2; first write to it happens in iter 0's
    // prefetch (tile 2), which is AFTER iter 0's top barrier -> all threads'
    // A-preload ldsm reads are complete by then.

    // Per-thread top-KEEP for 2 query rows (hi = 0/1 -> rows lane>>2, +8)
    float thr[2];
    float ts[2][KEEP]; int ti[2][KEEP];
    #pragma unroll
    for (int i = 0; i < 2; i++) {
        thr[i] = -CUDART_INF_F;
        #pragma unroll
        for (int j = 0; j < KEEP; j++) { ts[i][j] = -CUDART_INF_F; ti[i][j] = -1; }
    }

    for (int i = 0; i < nt; i++) {
        if (i + 1 < nt) CP_WAIT(1); else CP_WAIT(0);   // tile i landed
        __syncthreads();                               // single barrier/tile
        const uint32_t kbuf = kb3[i % 3];

        // Prefetch tile i+2 into buf[(i+2)%3] (= tile i-1's buffer, dead).
        // Issued before the MMA block so loads overlap compute.
        if (i + 2 < nt) {
            size_t ksrc = __cvta_generic_to_global(
                g_kbf + (size_t)(tstart + i + 2) * TILE * DIM);
            const uint32_t pbuf = kb3[(i + 2) % 3];
            #pragma unroll
            for (int m = 0; m < 8; m++) {
                int idx = m * NTHREADS + tid;
                int row = idx >> 5, c16 = idx & 31;
                CP16(pbuf + tile_off(row, c16), ksrc + (size_t)row * (DIM*2) + c16 * 16);
            }
            CP_COMMIT();
        }

        uint32_t acc[8][2];                  // [n8 block][creg], f16x2 packed
        #pragma unroll
        for (int nb = 0; nb < 8; nb++) acc[nb][0] = acc[nb][1] = 0u;

        #pragma unroll
        for (int ks = 0; ks < 16; ks++) {    // 16 dims per step, n64 in 2 halves
            #pragma unroll
            for (int nh = 0; nh < 2; nh++) { // keep only 8 B regs live
                uint32_t b0, b1, b2, b3, b4, b5, b6, b7;
                int nb0 = nw + nh * 32;
                ldsm_x4(b0, b1, b2, b3, kbuf + tile_off(nb0 + b_r,      ks * 2 + b_kc));
                ldsm_x4(b4, b5, b6, b7, kbuf + tile_off(nb0 + 16 + b_r, ks * 2 + b_kc));
                mma16816_f16(acc[nh*4+0][0], acc[nh*4+0][1], aF[ks][0], aF[ks][1], aF[ks][2], aF[ks][3], b0, b1);
                mma16816_f16(acc[nh*4+1][0], acc[nh*4+1][1], aF[ks][0], aF[ks][1], aF[ks][2], aF[ks][3], b2, b3);
                mma16816_f16(acc[nh*4+2][0], acc[nh*4+2][1], aF[ks][0], aF[ks][1], aF[ks][2], aF[ks][3], b4, b5);
                mma16816_f16(acc[nh*4+3][0], acc[nh*4+3][1], aF[ks][0], aF[ks][1], aF[ks][2], aF[ks][3], b6, b7);
            }
        }

        // Fold: packed hmax2 screen per row; full fold only if screen passes.
        const int colbase = (tstart + i) * TILE + nw + (lane & 3) * 2;
        #pragma unroll
        for (int hi = 0; hi < 2; hi++) {
            __half2 m01 = __hmax2(*(__half2*)&acc[0][hi], *(__half2*)&acc[1][hi]);
            __half2 m23 = __hmax2(*(__half2*)&acc[2][hi], *(__half2*)&acc[3][hi]);
            __half2 m45 = __hmax2(*(__half2*)&acc[4][hi], *(__half2*)&acc[5][hi]);
            __half2 m67 = __hmax2(*(__half2*)&acc[6][hi], *(__half2*)&acc[7][hi]);
            __half2 m   = __hmax2(__hmax2(m01, m23), __hmax2(m45, m67));
            float2 mf = __half22float2(m);
            if (fmaxf(mf.x, mf.y) > thr[hi]) {       // rare path
                #pragma unroll
                for (int nb = 0; nb < 8; nb++) {
                    float2 v = __half22float2(*(__half2*)&acc[nb][hi]);
                    #pragma unroll
                    for (int e = 0; e < 2; e++) {
                        float sc = e ? v.y : v.x;
                        if (sc > thr[hi]) {
                            int key = colbase + nb * 8 + e;
                            int ms = 0; float mv = ts[hi][0];
                            #pragma unroll
                            for (int t = 1; t < KEEP; t++)
                                if (ts[hi][t] < mv) { mv = ts[hi][t]; ms = t; }
                            ts[hi][ms] = sc; ti[hi][ms] = key;
                            mv = ts[hi][0];
                            #pragma unroll
                            for (int t = 1; t < KEEP; t++) mv = fminf(mv, ts[hi][t]);
                            thr[hi] = mv;
                        }
                    }
                }
            }
        }
    }

    // ---- Merge: 8 holders x KEEP entries per query row -> top-8 per (q,slice)
    __syncthreads();
    float2* Cand = (float2*)smem;            // 128 rows x 32 float2 = 32 KB
    const int holder = (w >> 3) * 4 + (lane & 3);
    #pragma unroll
    for (int hi = 0; hi < 2; hi++) {
        int row = mw + (lane >> 2) + hi * 8;
        float2* dst = Cand + row * (8 * KEEP) + holder * KEEP;
        #pragma unroll
        for (int j = 0; j < KEEP; j++)
            dst[j] = make_float2(ts[hi][j], __int_as_float(ti[hi][j]));
    }
    __syncthreads();

    if (tid < TQ) {
        const float2* c = Cand + tid * (8 * KEEP);
        float bthr = -CUDART_INF_F;
        float bs[8]; int bi[8];
        #pragma unroll
        for (int j = 0; j < 8; j++) { bs[j] = -CUDART_INF_F; bi[j] = -1; }
        for (int t = 0; t < 8 * KEEP; t++) {
            float sc = c[t].x;
            if (sc > bthr) {
                int ms = 0; float mv = bs[0];
                #pragma unroll
                for (int u = 1; u < 8; u++)
                    if (bs[u] < mv) { mv = bs[u]; ms = u; }
                bs[ms] = sc; bi[ms] = __float_as_int(c[t].y);
                mv = bs[0];
                #pragma unroll
                for (int u = 1; u < 8; u++) mv = fminf(mv, bs[u]);
                bthr = mv;
            }
        }
        float2* dst = g_part + ((size_t)(qb + tid) * KT + slice) * TOPK;
        #pragma unroll
        for (int j = 0; j < 8; j++)
            dst[j] = make_float2(bs[j], __int_as_float(bi[j]));
    }
}

// ---------------------------------------------------------------------------
// Kernel C: prune 144 candidates to top-PRUNE by approx score (pairwise rank),
// exact fp32 rescore of those, exact top-8 with (score desc, index asc)
// tie-break, then gather keys+values.
// ---------------------------------------------------------------------------
#define RT 256
__global__ void __launch_bounds__(RT) rescore_kernel(
    const float* __restrict__ query, const float* __restrict__ keys,
    const float* __restrict__ values, float* __restrict__ out)
{
    __shared__ __align__(16) float qs[DIM];
    __shared__ float csc[NCAND];
    __shared__ int   cidx[NCAND];
    __shared__ int   sel[PRUNE];
    __shared__ int   nsel;
    __shared__ float ssc[PRUNE];
    __shared__ float rs[RT];
    __shared__ int   ri[RT];
    __shared__ int   rp[RT];
    __shared__ int   topidx[TOPK];

    const int q = blockIdx.x, tid = threadIdx.x, w = tid >> 5, l = tid & 31;

    qs[tid] = query[(size_t)q * DIM + tid];
    if (tid == 0) nsel = 0;
    if (tid < NCAND) {
        float2 c = g_part[(size_t)q * NCAND + tid];
        csc[tid] = c.x;
        cidx[tid] = __float_as_int(c.y);
    }
    __syncthreads();

    // Pairwise rank by approx score (desc, idx asc); keep rank < PRUNE.
    // All (score, idx) pairs are distinct -> exactly PRUNE selected.
    if (tid < NCAND) {
        float s = csc[tid]; int ix = cidx[tid];
        int rank = 0;
        for (int j = 0; j < NCAND; j++) {
            float sj = csc[j]; int xj = cidx[j];
            rank += (sj > s) || (sj == s && xj < ix);
        }
        if (rank < PRUNE) {
            int p = atomicAdd(&nsel, 1);
            sel[p] = ix;
        }
    }
    __syncthreads();

    // Warp-per-candidate exact scoring: 8 warps x 3 candidates
    for (int cc = w * (PRUNE / 8); cc < (w + 1) * (PRUNE / 8); cc++) {
        int idx = sel[cc];
        float s = -CUDART_INF_F;
        if (idx >= 0) {
            float ksc = g_kscale[idx];
            const float* kr = keys + (size_t)idx * DIM;
            float4 ka = *(const float4*)(kr + l * 8);
            float4 kb = *(const float4*)(kr + l * 8 + 4);
            float4 qa = ((const float4*)qs)[l * 2];
            float4 qb = ((const float4*)qs)[l * 2 + 1];
            float p = ka.x*qa.x + ka.y*qa.y + ka.z*qa.z + ka.w*qa.w
                    + kb.x*qb.x + kb.y*qb.y + kb.z*qb.z + kb.w*qb.w;
            #pragma unroll
            for (int off = 16; off; off >>= 1) p += __shfl_xor_sync(0xffffffffu, p, off);
            s = (ksc == 0.0f) ? -CUDART_INF_F : p * ksc;
        }
        if (l == 0) ssc[cc] = s;
    }
    __syncthreads();

    // 8 rounds of exact argmax over PRUNE entries with index tie-break
    for (int r = 0; r < TOPK; r++) {
        float s = (tid < PRUNE) ? ssc[tid] : -CUDART_INF_F;
        rs[tid] = s;
        ri[tid] = (tid < PRUNE && s != -CUDART_INF_F) ? sel[tid] : 0x7fffffff;
        rp[tid] = tid;
        __syncthreads();
        for (int off = RT / 2; off > 0; off >>= 1) {
            if (tid < off) {
                float s2 = rs[tid + off]; int ix2 = ri[tid + off];
                if (s2 > rs[tid] || (s2 == rs[tid] && ix2 < ri[tid])) {
                    rs[tid] = s2; ri[tid] = ix2; rp[tid] = rp[tid + off];
                }
            }
            __syncthreads();
        }
        if (tid == 0) {
            topidx[r] = ri[0];
            if (rp[0] < PRUNE) ssc[rp[0]] = -CUDART_INF_F;   // consume winner
        }
        __syncthreads();
    }

    // Gather: out = [gathered_keys (B,K,D) | gathered_vals (B,K,D)]
    const size_t GK = (size_t)BQ * TOPK * DIM;
    for (int i = tid; i < TOPK * DIM / 4; i += RT) {
        int j  = i >> 6;
        int c4 = i & 63;
        int ix = topidx[j];
        if (ix < 0 || ix == 0x7fffffff) ix = 0;  // defensive
        float4 kv = *(const float4*)(keys   + (size_t)ix * DIM + c4 * 4);
        float4 vv = *(const float4*)(values + (size_t)ix * DIM + c4 * 4);
        *(float4*)(out +      ((size_t)q * TOPK + j) * DIM + c4 * 4) = kv;
        *(float4*)(out + GK + ((size_t)q * TOPK + j) * DIM + c4 * 4) = vv;
    }
}

// ---------------------------------------------------------------------------
extern "C" void kernel_launch(void* const* d_in, const int* in_sizes, int n_in,
                              void* d_out, int out_size)
{
    const float*         query  = (const float*)d_in[0];
    const float*         keys   = (const float*)d_in[1];
    const float*         values = (const float*)d_in[2];
    const unsigned char* valid  = (const unsigned char*)d_in[3];
    // d_in[4] (top_k) fixed at 8.

    cudaFuncSetAttribute(score_mma_kernel,
                         cudaFuncAttributeMaxDynamicSharedMemorySize, SM_TOTAL);

    convert_kernel<<<NKEYS / 8 + BQ * DIM / 256, 256>>>(keys, query, valid);
    dim3 grid(KT, QT);
    score_mma_kernel<<<grid, NTHREADS, SM_TOTAL>>>();
    rescore_kernel<<<BQ, RT>>>(query, keys, values, (float*)d_out);
}